// round 1
// baseline (speedup 1.0000x reference)
#include <cuda_runtime.h>
#include <cstdint>

#define Bn 8
#define Nn 2048
#define Fn 512
#define NEGV (-10000.0f)
#define SLOPEV 0.2f

// Scratch (allocation-free rule: __device__ globals)
__device__ float g_hidden[Bn * Nn * Fn];   // 33.5 MB
__device__ float g_s[Bn * Nn];
__device__ float g_d[Bn * Nn];
__device__ float g_m[Bn * Nn];
__device__ float g_l[Bn * Nn];

// ---------------------------------------------------------------------------
// Kernel 1: hidden = text @ W + bias
// Block tile: 32 rows x 512 cols, BK=16. 256 threads, each 4 rows x 16 cols.
// ---------------------------------------------------------------------------
__global__ __launch_bounds__(256, 2)
void k_hidden(const float* __restrict__ text,
              const float* __restrict__ W,
              const float* __restrict__ bias) {
    __shared__ float sA[32][16];        // text tile
    __shared__ float sB[16][512];       // W tile

    const int row0 = blockIdx.x * 32;   // gridDim.x = 16384/32 = 512
    const int tid = threadIdx.x;
    const int ty = tid >> 5;            // 0..7
    const int tx = tid & 31;            // 0..31

    float acc[4][16];
    #pragma unroll
    for (int r = 0; r < 4; r++)
        #pragma unroll
        for (int c = 0; c < 16; c++) acc[r][c] = 0.0f;

    for (int k0 = 0; k0 < Fn; k0 += 16) {
        // load text tile: 32x16
        for (int i = tid; i < 32 * 16; i += 256) {
            int r = i >> 4, c = i & 15;
            sA[r][c] = text[(size_t)(row0 + r) * Fn + k0 + c];
        }
        // load W tile: 16x512 (float4)
        for (int i = tid; i < 16 * 512 / 4; i += 256) {
            int r = i >> 7, c4 = i & 127;
            ((float4*)sB[r])[c4] = ((const float4*)(W + (size_t)(k0 + r) * Fn))[c4];
        }
        __syncthreads();
        #pragma unroll
        for (int kk = 0; kk < 16; kk++) {
            float a[4];
            #pragma unroll
            for (int r = 0; r < 4; r++) a[r] = sA[ty + 8 * r][kk];
            #pragma unroll
            for (int g = 0; g < 4; g++) {
                float4 w4 = *(const float4*)&sB[kk][tx * 4 + 128 * g];
                #pragma unroll
                for (int r = 0; r < 4; r++) {
                    acc[r][4 * g + 0] += a[r] * w4.x;
                    acc[r][4 * g + 1] += a[r] * w4.y;
                    acc[r][4 * g + 2] += a[r] * w4.z;
                    acc[r][4 * g + 3] += a[r] * w4.w;
                }
            }
        }
        __syncthreads();
    }

    // epilogue: add bias, store
    #pragma unroll
    for (int r = 0; r < 4; r++) {
        int row = row0 + ty + 8 * r;
        #pragma unroll
        for (int g = 0; g < 4; g++) {
            int f = tx * 4 + 128 * g;
            float4 o;
            o.x = acc[r][4 * g + 0] + bias[f + 0];
            o.y = acc[r][4 * g + 1] + bias[f + 1];
            o.z = acc[r][4 * g + 2] + bias[f + 2];
            o.w = acc[r][4 * g + 3] + bias[f + 3];
            *(float4*)&g_hidden[(size_t)row * Fn + f] = o;
        }
    }
}

// ---------------------------------------------------------------------------
// Kernel 2: s = hidden . a_src ; d = hidden . a_dst   (per node)
// ---------------------------------------------------------------------------
__global__ __launch_bounds__(128)
void k_sd(const float* __restrict__ a_src, const float* __restrict__ a_dst) {
    const int row = blockIdx.x;          // B*N blocks
    const int tid = threadIdx.x;
    const float* h = g_hidden + (size_t)row * Fn;
    float ss = 0.0f, dd = 0.0f;
    for (int f = tid; f < Fn; f += 128) {
        float v = h[f];
        ss += v * a_src[f];
        dd += v * a_dst[f];
    }
    #pragma unroll
    for (int off = 16; off > 0; off >>= 1) {
        ss += __shfl_down_sync(0xffffffffu, ss, off);
        dd += __shfl_down_sync(0xffffffffu, dd, off);
    }
    __shared__ float rs[4], rd[4];
    if ((tid & 31) == 0) { rs[tid >> 5] = ss; rd[tid >> 5] = dd; }
    __syncthreads();
    if (tid == 0) {
        g_s[row] = rs[0] + rs[1] + rs[2] + rs[3];
        g_d[row] = rd[0] + rd[1] + rd[2] + rd[3];
    }
}

// ---------------------------------------------------------------------------
// Kernel 3: per-row softmax stats (m, l) over masked leaky scores
// ---------------------------------------------------------------------------
__global__ __launch_bounds__(256)
void k_stats(const int* __restrict__ adj) {
    const int row = blockIdx.x;          // b*N + i
    const int b = row / Nn;
    const int tid = threadIdx.x;
    const float si = g_s[row];
    const int* arow = adj + (size_t)row * Nn;
    const float* drow = g_d + (size_t)b * Nn;

    float m = -1e30f, l = 0.0f;
    for (int j = tid; j < Nn; j += 256) {
        float sc = si + drow[j];
        sc = (sc >= 0.0f) ? sc : SLOPEV * sc;
        if (arow[j]) sc = NEGV;
        if (sc > m) {
            l = l * __expf(m - sc) + 1.0f;
            m = sc;
        } else {
            l += __expf(sc - m);
        }
    }
    __shared__ float sm[256], sl[256];
    sm[tid] = m; sl[tid] = l;
    __syncthreads();
    for (int s = 128; s > 0; s >>= 1) {
        if (tid < s) {
            float m1 = sm[tid], l1 = sl[tid];
            float m2 = sm[tid + s], l2 = sl[tid + s];
            float mm = fmaxf(m1, m2);
            sl[tid] = l1 * __expf(m1 - mm) + l2 * __expf(m2 - mm);
            sm[tid] = mm;
        }
        __syncthreads();
    }
    if (tid == 0) { g_m[row] = sm[0]; g_l[row] = sl[0]; }
}

// ---------------------------------------------------------------------------
// Kernel 4: out = softmax(scores) @ hidden   (P recomputed on the fly)
// Block tile: 32 rows x 512 cols, K-tile = 16 over j. 256 threads, 4x16 micro.
// grid: (N/32, B)
// ---------------------------------------------------------------------------
__global__ __launch_bounds__(256, 2)
void k_pv(const int* __restrict__ adj, float* __restrict__ out) {
    __shared__ float sH[16][512];        // hidden tile  (32 KB)
    __shared__ float sP[32][17];         // P tile (padded)
    __shared__ float s_s[32], s_m[32], s_linv[32];

    const int b = blockIdx.y;
    const int i0 = blockIdx.x * 32;
    const int tid = threadIdx.x;
    const int ty = tid >> 5;
    const int tx = tid & 31;
    const int rowbase = b * Nn + i0;

    if (tid < 32) {
        s_s[tid] = g_s[rowbase + tid];
        s_m[tid] = g_m[rowbase + tid];
        s_linv[tid] = 1.0f / g_l[rowbase + tid];
    }

    float acc[4][16];
    #pragma unroll
    for (int r = 0; r < 4; r++)
        #pragma unroll
        for (int c = 0; c < 16; c++) acc[r][c] = 0.0f;

    __syncthreads();

    const float* drow = g_d + (size_t)b * Nn;
    for (int j0 = 0; j0 < Nn; j0 += 16) {
        // load hidden tile: 16 x 512 (float4)
        const float* hb = g_hidden + ((size_t)b * Nn + j0) * Fn;
        for (int i = tid; i < 16 * 512 / 4; i += 256) {
            int r = i >> 7, c4 = i & 127;
            ((float4*)sH[r])[c4] = ((const float4*)(hb + (size_t)r * Fn))[c4];
        }
        // compute P tile: 32 x 16
        #pragma unroll
        for (int idx = tid; idx < 32 * 16; idx += 256) {
            int r = idx >> 4, kk = idx & 15;
            int j = j0 + kk;
            float sc = s_s[r] + drow[j];
            sc = (sc >= 0.0f) ? sc : SLOPEV * sc;
            if (adj[((size_t)(rowbase + r)) * Nn + j]) sc = NEGV;
            sP[r][kk] = __expf(sc - s_m[r]);
        }
        __syncthreads();
        #pragma unroll
        for (int kk = 0; kk < 16; kk++) {
            float p[4];
            #pragma unroll
            for (int r = 0; r < 4; r++) p[r] = sP[ty + 8 * r][kk];
            #pragma unroll
            for (int g = 0; g < 4; g++) {
                float4 h4 = *(const float4*)&sH[kk][tx * 4 + 128 * g];
                #pragma unroll
                for (int r = 0; r < 4; r++) {
                    acc[r][4 * g + 0] += p[r] * h4.x;
                    acc[r][4 * g + 1] += p[r] * h4.y;
                    acc[r][4 * g + 2] += p[r] * h4.z;
                    acc[r][4 * g + 3] += p[r] * h4.w;
                }
            }
        }
        __syncthreads();
    }

    // epilogue: divide by l, store
    #pragma unroll
    for (int r = 0; r < 4; r++) {
        int ri = ty + 8 * r;
        float inv = s_linv[ri];
        size_t obase = ((size_t)(rowbase + ri)) * Fn;
        #pragma unroll
        for (int g = 0; g < 4; g++) {
            int f = tx * 4 + 128 * g;
            float4 o;
            o.x = acc[r][4 * g + 0] * inv;
            o.y = acc[r][4 * g + 1] * inv;
            o.z = acc[r][4 * g + 2] * inv;
            o.w = acc[r][4 * g + 3] * inv;
            *(float4*)&out[obase + f] = o;
        }
    }
}

// ---------------------------------------------------------------------------
extern "C" void kernel_launch(void* const* d_in, const int* in_sizes, int n_in,
                              void* d_out, int out_size) {
    const float* text  = (const float*)d_in[0];
    const int*   adj   = (const int*)  d_in[1];
    const float* W     = (const float*)d_in[2];
    const float* bias  = (const float*)d_in[3];
    const float* a_src = (const float*)d_in[4];
    const float* a_dst = (const float*)d_in[5];
    float* out = (float*)d_out;

    k_hidden<<<(Bn * Nn) / 32, 256>>>(text, W, bias);
    k_sd<<<Bn * Nn, 128>>>(a_src, a_dst);
    k_stats<<<Bn * Nn, 256>>>(adj);
    dim3 g4(Nn / 32, Bn);
    k_pv<<<g4, 256>>>(adj, out);
}

// round 3
// speedup vs baseline: 3.2063x; 3.2063x over previous
#include <cuda_runtime.h>
#include <cstdint>

#define Bn 8
#define Nn 2048
#define Fn 512

// ---------------------------------------------------------------------------
// Scratch (__device__ globals; no allocation allowed)
// ---------------------------------------------------------------------------
__device__ float g_hidden[Bn * Nn * Fn];   // tf32-rounded hidden, 33.5 MB
__device__ float g_Wr[Fn * Fn];            // tf32-rounded W
__device__ float g_s[Bn * Nn];
__device__ float g_d[Bn * Nn];

// ---------------------------------------------------------------------------
// Helpers
// ---------------------------------------------------------------------------
__device__ __forceinline__ uint32_t smem_u32(const void* p) {
    uint32_t a;
    asm("{ .reg .u64 t; cvta.to.shared.u64 t, %1; cvt.u32.u64 %0, t; }"
        : "=r"(a) : "l"(p));
    return a;
}
__device__ __forceinline__ uint32_t f2tf32(float v) {
    uint32_t r;
    asm("cvt.rna.tf32.f32 %0, %1;" : "=r"(r) : "f"(v));
    return r;
}
__device__ __forceinline__ void cp16(uint32_t dst, const void* src) {
    asm volatile("cp.async.cg.shared.global [%0], [%1], 16;"
                 :: "r"(dst), "l"(src));
}
#define CP_COMMIT() asm volatile("cp.async.commit_group;" ::: "memory")
#define CP_WAIT0()  asm volatile("cp.async.wait_group 0;" ::: "memory")

__device__ __forceinline__ void mma8(float* c, uint32_t a0, uint32_t a1,
                                     uint32_t a2, uint32_t a3,
                                     uint32_t b0, uint32_t b1) {
    asm volatile("mma.sync.aligned.m16n8k8.row.col.f32.tf32.tf32.f32 "
        "{%0,%1,%2,%3},{%4,%5,%6,%7},{%8,%9},{%0,%1,%2,%3};"
        : "+f"(c[0]), "+f"(c[1]), "+f"(c[2]), "+f"(c[3])
        : "r"(a0), "r"(a1), "r"(a2), "r"(a3), "r"(b0), "r"(b1));
}

// Fast exp via exp2 polynomial on FMA pipe (rel err ~2e-6).
__device__ __forceinline__ float exp_fast(float x) {
    float y = x * 1.4426950408889634f;
    y = fmaxf(y, -125.0f);
    float z = y + 12582912.0f;
    int   ei = __float_as_int(z) - 0x4B400000;
    float f = y - (z - 12582912.0f);
    float p = 1.3333558146e-3f;
    p = fmaf(p, f, 9.6181291076e-3f);
    p = fmaf(p, f, 5.5504108664e-2f);
    p = fmaf(p, f, 2.4022650695e-1f);
    p = fmaf(p, f, 6.9314718056e-1f);
    p = fmaf(p, f, 1.0f);
    return p * __int_as_float((ei + 127) << 23);
}

// ---------------------------------------------------------------------------
// kW: round W to tf32 once (so kA can cp.async it raw)
// ---------------------------------------------------------------------------
__global__ __launch_bounds__(256)
void kW(const float* __restrict__ W) {
    int i = blockIdx.x * 256 + threadIdx.x;          // grid 256 -> 65536 float4
    float4 v = ((const float4*)W)[i];
    float4 o;
    o.x = __uint_as_float(f2tf32(v.x));
    o.y = __uint_as_float(f2tf32(v.y));
    o.z = __uint_as_float(f2tf32(v.z));
    o.w = __uint_as_float(f2tf32(v.w));
    ((float4*)g_Wr)[i] = o;
}

// ---------------------------------------------------------------------------
// kA: hidden = text @ W + b (tf32 mma.sync). Block 128x128, 8 warps (2m x 4n),
// warp tile 64x32, K-tile 32. Stores tf32-rounded hidden (fp32 container).
// smem: A 2*128*36*4 = 36864 ; B 2*32*136*4 = 34816 ; total 71680
// ---------------------------------------------------------------------------
#define SA 36
#define SBA 136

__global__ __launch_bounds__(256, 2)
void kA(const float* __restrict__ text, const float* __restrict__ bias) {
    extern __shared__ unsigned char smraw[];
    uint32_t* Ast = (uint32_t*)smraw;
    uint32_t* Bst = (uint32_t*)(smraw + 36864);
    const uint32_t sb = smem_u32(smraw);

    const int tid = threadIdx.x;
    const int w = tid >> 5, lane = tid & 31;
    const int g = lane >> 2, tg = lane & 3;
    const int wm = w >> 2, wn = w & 3;
    const int row0 = blockIdx.x * 128;
    const int f0 = blockIdx.y * 128;

    float acc[4][4][4];
    #pragma unroll
    for (int mf = 0; mf < 4; mf++)
        #pragma unroll
        for (int nf = 0; nf < 4; nf++)
            #pragma unroll
            for (int q = 0; q < 4; q++) acc[mf][nf][q] = 0.0f;

    float4 pf[4];

    // prefetch A(0) to regs, issue B(0) cp.async
    {
        const float* src = text + (size_t)row0 * Fn;
        #pragma unroll
        for (int q = 0; q < 4; q++) {
            int idx = tid + 256 * q, r = idx >> 3, c4 = idx & 7;
            pf[q] = *(const float4*)(src + (size_t)r * Fn + c4 * 4);
        }
        const float* wsrc = g_Wr + f0;
        #pragma unroll
        for (int q = 0; q < 4; q++) {
            int idx = tid + 256 * q, k = idx >> 5, nc = idx & 31;
            cp16(sb + 36864u + (uint32_t)(k * SBA + nc * 4) * 4,
                 wsrc + (size_t)k * Fn + nc * 4);
        }
        CP_COMMIT();
    }

    #pragma unroll 1
    for (int c = 0; c < 16; c++) {
        const int buf = c & 1;
        CP_WAIT0();
        __syncthreads();

        // store A(c) regs -> smem (cvt to tf32)
        {
            uint32_t* A = Ast + buf * 128 * SA;
            #pragma unroll
            for (int q = 0; q < 4; q++) {
                int idx = tid + 256 * q, r = idx >> 3, c4 = idx & 7;
                A[r * SA + c4 * 4 + 0] = f2tf32(pf[q].x);
                A[r * SA + c4 * 4 + 1] = f2tf32(pf[q].y);
                A[r * SA + c4 * 4 + 2] = f2tf32(pf[q].z);
                A[r * SA + c4 * 4 + 3] = f2tf32(pf[q].w);
            }
        }
        if (c < 15) {
            // issue B(c+1), prefetch A(c+1)
            const int nb = (c + 1) & 1;
            const float* wsrc = g_Wr + (size_t)((c + 1) * 32) * Fn + f0;
            #pragma unroll
            for (int q = 0; q < 4; q++) {
                int idx = tid + 256 * q, k = idx >> 5, nc = idx & 31;
                cp16(sb + 36864u + (uint32_t)(nb * 32 * SBA + k * SBA + nc * 4) * 4,
                     wsrc + (size_t)k * Fn + nc * 4);
            }
            CP_COMMIT();
            const float* src = text + (size_t)row0 * Fn + (c + 1) * 32;
            #pragma unroll
            for (int q = 0; q < 4; q++) {
                int idx = tid + 256 * q, r = idx >> 3, c4 = idx & 7;
                pf[q] = *(const float4*)(src + (size_t)r * Fn + c4 * 4);
            }
        }
        __syncthreads();

        // MMA on buffer buf
        {
            const uint32_t* A = Ast + buf * 128 * SA;
            const uint32_t* B = Bst + buf * 32 * SBA;
            #pragma unroll
            for (int ks = 0; ks < 4; ks++) {
                const int kb = ks * 8;
                uint32_t bf[4][2];
                #pragma unroll
                for (int nf = 0; nf < 4; nf++) {
                    int nb2 = wn * 32 + nf * 8 + g;
                    bf[nf][0] = B[(kb + tg) * SBA + nb2];
                    bf[nf][1] = B[(kb + 4 + tg) * SBA + nb2];
                }
                #pragma unroll
                for (int mf = 0; mf < 4; mf++) {
                    int rb = wm * 64 + mf * 16;
                    uint32_t a0 = A[(rb + g) * SA + kb + tg];
                    uint32_t a1 = A[(rb + g + 8) * SA + kb + tg];
                    uint32_t a2 = A[(rb + g) * SA + kb + tg + 4];
                    uint32_t a3 = A[(rb + g + 8) * SA + kb + tg + 4];
                    #pragma unroll
                    for (int nf = 0; nf < 4; nf++)
                        mma8(acc[mf][nf], a0, a1, a2, a3, bf[nf][0], bf[nf][1]);
                }
            }
        }
    }

    // epilogue: + bias, round to tf32, store
    #pragma unroll
    for (int mf = 0; mf < 4; mf++) {
        int r0 = row0 + wm * 64 + mf * 16 + g;
        #pragma unroll
        for (int nf = 0; nf < 4; nf++) {
            int f = f0 + wn * 32 + nf * 8 + 2 * tg;
            float b0v = __ldg(bias + f), b1v = __ldg(bias + f + 1);
            float2 v0, v1;
            v0.x = __uint_as_float(f2tf32(acc[mf][nf][0] + b0v));
            v0.y = __uint_as_float(f2tf32(acc[mf][nf][1] + b1v));
            v1.x = __uint_as_float(f2tf32(acc[mf][nf][2] + b0v));
            v1.y = __uint_as_float(f2tf32(acc[mf][nf][3] + b1v));
            *(float2*)&g_hidden[(size_t)r0 * Fn + f] = v0;
            *(float2*)&g_hidden[(size_t)(r0 + 8) * Fn + f] = v1;
        }
    }
}

// ---------------------------------------------------------------------------
// kSD: s = hidden.a_src, d = hidden.a_dst per node
// ---------------------------------------------------------------------------
__global__ __launch_bounds__(128)
void kSD(const float* __restrict__ a_src, const float* __restrict__ a_dst) {
    const int row = blockIdx.x;
    const int tid = threadIdx.x;
    const float* h = g_hidden + (size_t)row * Fn;
    float ss = 0.0f, dd = 0.0f;
    for (int f = tid; f < Fn; f += 128) {
        float v = h[f];
        ss = fmaf(v, a_src[f], ss);
        dd = fmaf(v, a_dst[f], dd);
    }
    #pragma unroll
    for (int off = 16; off > 0; off >>= 1) {
        ss += __shfl_down_sync(0xffffffffu, ss, off);
        dd += __shfl_down_sync(0xffffffffu, dd, off);
    }
    __shared__ float rs[4], rd[4];
    if ((tid & 31) == 0) { rs[tid >> 5] = ss; rd[tid >> 5] = dd; }
    __syncthreads();
    if (tid == 0) {
        g_s[row] = rs[0] + rs[1] + rs[2] + rs[3];
        g_d[row] = rd[0] + rd[1] + rd[2] + rd[3];
    }
}

// ---------------------------------------------------------------------------
// kB: fused mask + leakyReLU + exp + PV GEMM. Block 128 rows x 256 feats,
// 8 warps (2m x 4n), warp tile 64x64, K(j)-tile 32, 64 ktiles.
// smem (bytes): Ps 0..36864 | Bs 36864..104448 | Aj 104448..137216 |
//               s_s 137216 | s_l 137728 | s_d 138240..146432
// ---------------------------------------------------------------------------
#define SBB 264
#define PS_OFF  0u
#define BS_OFF  36864u
#define AJ_OFF  104448u
#define SS_OFF  137216u
#define SL_OFF  137728u
#define SD_OFF  138240u
#define KB_SMEM 146432

__global__ __launch_bounds__(256, 1)
void kB(const int* __restrict__ adj, float* __restrict__ out) {
    extern __shared__ unsigned char smraw[];
    uint32_t* Ps  = (uint32_t*)(smraw + PS_OFF);
    uint32_t* Bst = (uint32_t*)(smraw + BS_OFF);
    int*      Aj  = (int*)     (smraw + AJ_OFF);
    float*    s_s = (float*)   (smraw + SS_OFF);
    float*    s_l = (float*)   (smraw + SL_OFF);
    float*    s_d = (float*)   (smraw + SD_OFF);
    const uint32_t sb = smem_u32(smraw);

    const int tid = threadIdx.x;
    const int w = tid >> 5, lane = tid & 31;
    const int g = lane >> 2, tg = lane & 3;
    const int wm = w & 1, wn = w >> 1;
    const int it = blockIdx.x, nh = blockIdx.y, b = blockIdx.z;
    const int i0 = it * 128;
    const int f0 = nh * 256;
    const size_t rowg = (size_t)b * Nn + i0;   // global row base (adj/s/out)

    if (tid < 128) s_s[tid] = g_s[rowg + tid];
    for (int i = tid; i < Nn; i += 256) s_d[i] = g_d[b * Nn + i];

    float acc[4][8][4];
    #pragma unroll
    for (int mf = 0; mf < 4; mf++)
        #pragma unroll
        for (int nf = 0; nf < 8; nf++)
            #pragma unroll
            for (int q = 0; q < 4; q++) acc[mf][nf][q] = 0.0f;

    float lpart[16];
    #pragma unroll
    for (int p = 0; p < 16; p++) lpart[p] = 0.0f;

    // issue group 0: B tile (hidden) + adj tile
    {
        const float* hsrc = g_hidden + ((size_t)b * Nn) * Fn + f0;
        #pragma unroll
        for (int q = 0; q < 8; q++) {
            int idx = tid + 256 * q, k = idx >> 6, nc = idx & 63;
            cp16(sb + BS_OFF + (uint32_t)(k * SBB + nc * 4) * 4,
                 hsrc + (size_t)k * Fn + nc * 4);
        }
        const int* asrc = adj + rowg * Nn;
        #pragma unroll
        for (int q = 0; q < 4; q++) {
            int idx = tid + 256 * q, r = idx >> 3, c4 = idx & 7;
            cp16(sb + AJ_OFF + (uint32_t)(r * 32 + c4 * 4) * 4,
                 asrc + (size_t)r * Nn + c4 * 4);
        }
        CP_COMMIT();
    }

    #pragma unroll 1
    for (int c = 0; c < 64; c++) {
        const int buf = c & 1;
        CP_WAIT0();
        __syncthreads();

        if (c < 63) {
            const int nb = (c + 1) & 1;
            const float* hsrc = g_hidden + ((size_t)(b * Nn + (c + 1) * 32)) * Fn + f0;
            #pragma unroll
            for (int q = 0; q < 8; q++) {
                int idx = tid + 256 * q, k = idx >> 6, nc = idx & 63;
                cp16(sb + BS_OFF + (uint32_t)(nb * 32 * SBB + k * SBB + nc * 4) * 4,
                     hsrc + (size_t)k * Fn + nc * 4);
            }
            const int* asrc = adj + rowg * Nn + (c + 1) * 32;
            #pragma unroll
            for (int q = 0; q < 4; q++) {
                int idx = tid + 256 * q, r = idx >> 3, c4 = idx & 7;
                cp16(sb + AJ_OFF + (uint32_t)(nb * 4096 + r * 32 + c4 * 4) * 4,
                     asrc + (size_t)r * Nn + c4 * 4);
            }
            CP_COMMIT();
        }

        // build P tile from staged adj
        {
            const int* aj = Aj + buf * 4096;
            uint32_t* P = Ps + buf * 128 * SA;
            const float dj = s_d[c * 32 + lane];
            #pragma unroll
            for (int p = 0; p < 16; p++) {
                int r = 8 * p + w;
                int m = aj[r * 32 + lane];
                float sc = s_s[r] + dj;
                sc = (sc >= 0.0f) ? sc : 0.2f * sc;
                if (m) sc = -10000.0f;
                uint32_t tv = f2tf32(exp_fast(sc));
                lpart[p] += __uint_as_float(tv);
                P[r * SA + lane] = tv;
            }
        }
        __syncthreads();

        // MMA on buffer buf
        {
            const uint32_t* A = Ps + buf * 128 * SA;
            const uint32_t* B = Bst + buf * 32 * SBB;
            #pragma unroll
            for (int ks = 0; ks < 4; ks++) {
                const int kb = ks * 8;
                uint32_t bf[8][2];
                #pragma unroll
                for (int nf = 0; nf < 8; nf++) {
                    int nb2 = wn * 64 + nf * 8 + g;
                    bf[nf][0] = B[(kb + tg) * SBB + nb2];
                    bf[nf][1] = B[(kb + 4 + tg) * SBB + nb2];
                }
                #pragma unroll
                for (int mf = 0; mf < 4; mf++) {
                    int rb = wm * 64 + mf * 16;
                    uint32_t a0 = A[(rb + g) * SA + kb + tg];
                    uint32_t a1 = A[(rb + g + 8) * SA + kb + tg];
                    uint32_t a2 = A[(rb + g) * SA + kb + tg + 4];
                    uint32_t a3 = A[(rb + g + 8) * SA + kb + tg + 4];
                    #pragma unroll
                    for (int nf = 0; nf < 8; nf++)
                        mma8(acc[mf][nf], a0, a1, a2, a3, bf[nf][0], bf[nf][1]);
                }
            }
        }
        __syncthreads();
    }

    // reduce row sums -> s_l, invert
    #pragma unroll
    for (int p = 0; p < 16; p++) {
        float v = lpart[p];
        #pragma unroll
        for (int off = 16; off > 0; off >>= 1)
            v += __shfl_xor_sync(0xffffffffu, v, off);
        if (lane == 0) s_l[8 * p + w] = v;
    }
    __syncthreads();
    if (tid < 128) s_l[tid] = 1.0f / s_l[tid];
    __syncthreads();

    // epilogue: scale by 1/l, store
    #pragma unroll
    for (int mf = 0; mf < 4; mf++) {
        int rl = wm * 64 + mf * 16 + g;
        float i0v = s_l[rl], i1v = s_l[rl + 8];
        size_t o0 = (rowg + rl) * Fn;
        size_t o1 = (rowg + rl + 8) * Fn;
        #pragma unroll
        for (int nf = 0; nf < 8; nf++) {
            int f = f0 + wn * 64 + nf * 8 + 2 * tg;
            float2 v0, v1;
            v0.x = acc[mf][nf][0] * i0v;
            v0.y = acc[mf][nf][1] * i0v;
            v1.x = acc[mf][nf][2] * i1v;
            v1.y = acc[mf][nf][3] * i1v;
            *(float2*)&out[o0 + f] = v0;
            *(float2*)&out[o1 + f] = v1;
        }
    }
}

// ---------------------------------------------------------------------------
extern "C" void kernel_launch(void* const* d_in, const int* in_sizes, int n_in,
                              void* d_out, int out_size) {
    const float* text  = (const float*)d_in[0];
    const int*   adj   = (const int*)  d_in[1];
    const float* W     = (const float*)d_in[2];
    const float* bias  = (const float*)d_in[3];
    const float* a_src = (const float*)d_in[4];
    const float* a_dst = (const float*)d_in[5];
    float* out = (float*)d_out;

    static int inited = 0;
    if (!inited) {
        cudaFuncSetAttribute(kA, cudaFuncAttributeMaxDynamicSharedMemorySize, 71680);
        cudaFuncSetAttribute(kB, cudaFuncAttributeMaxDynamicSharedMemorySize, KB_SMEM);
        inited = 1;
    }

    kW<<<256, 256>>>(W);
    kA<<<dim3(128, 4), 256, 71680>>>(text, bias);
    kSD<<<Bn * Nn, 128>>>(a_src, a_dst);
    kB<<<dim3(16, 2, 8), 256, KB_SMEM>>>(adj, out);
}